// round 15
// baseline (speedup 1.0000x reference)
#include <cuda_runtime.h>

#define NNODES 50000
#define NEDGES 800000
#define DIM 64
#define NSTEPS 5
#define WROW 384        // combined weight row: [0..191]=Wi cols, [192..383]=Wh cols
#define NROW 132        // node row: [0..63]=m(gathered h-sum), [68..131]=h
#define HOFF 68

typedef unsigned long long ull;

// Scratch (allocation-free __device__ globals), 16B-aligned.
// g_h is DOUBLE-BUFFERED: step l reads buf (l&1) (step 0 reads x), writes
// buf ((l+1)&1) (last step writes dout). Writers never touch the read
// buffer -> fused gather+GRU has no inter-block race.
// g_cnt invariant: ==0 at every kernel_launch entry (zero-init at load;
// re-zeroed by the final k_gru). Every call does identical work.
__device__ __align__(16) float g_h[2][NNODES * DIM];
__device__ __align__(16) float g_W[NSTEPS][64 * WROW];   // [k][ Wc[l] | whh^T ]
__device__ int g_csr_src[NEDGES];
__device__ int g_row[NNODES + 1];
__device__ int g_cnt[NNODES];

// ---------- packed f32x2 helpers ----------
__device__ __forceinline__ ull pack2(float lo, float hi) {
    ull r; asm("mov.b64 %0, {%1, %2};" : "=l"(r) : "f"(lo), "f"(hi)); return r;
}
__device__ __forceinline__ void fma2(ull& d, ull a, ull b) {
    asm("fma.rn.f32x2 %0, %1, %2, %0;" : "+l"(d) : "l"(a), "l"(b));
}
__device__ __forceinline__ float2 unpack2(ull v) {
    float2 r; asm("mov.b64 {%0, %1}, %2;" : "=f"(r.x), "=f"(r.y) : "l"(v)); return r;
}
__device__ __forceinline__ ull shfl_down16(ull v) {
    unsigned lo, hi;
    asm("mov.b64 {%0, %1}, %2;" : "=r"(lo), "=r"(hi) : "l"(v));
    lo = __shfl_down_sync(0xFFFFFFFFu, lo, 16);
    hi = __shfl_down_sync(0xFFFFFFFFu, hi, 16);
    ull r; asm("mov.b64 %0, {%1, %2};" : "=l"(r) : "r"(lo), "r"(hi));
    return r;
}
__device__ __forceinline__ float sigf(float x) { return 1.0f / (1.0f + __expf(-x)); }
__device__ __forceinline__ float tanh_f(float x) {
    float t = __expf(-2.0f * fabsf(x));
    return copysignf((1.0f - t) / (1.0f + t), x);
}

// ======================================================================
// K0 (launch #0): edge histogram + combined-weight precompute, one grid.
//   blocks [0,3125):    histogram of dst into g_cnt
//   blocks [3125,3365): g_W[l][k*WROW + j]       = dot(W[l][k][:], wih[j][:])
//   blocks [3365,3413): g_W[*][k*WROW + 192 + j] = whh[j][k] (replicated)
// ======================================================================
__global__ void __launch_bounds__(256) k_histprep(
    const int* __restrict__ dst, const float* __restrict__ W,
    const float* __restrict__ wih, const float* __restrict__ whh)
{
    int b = blockIdx.x, t = threadIdx.x;
    if (b < 3125) {
        int e = b * 256 + t;
        if (e < NEDGES) atomicAdd(&g_cnt[__ldg(dst + e)], 1);
    } else if (b < 3365) {
        int idx = (b - 3125) * 256 + t;      // 0..61439
        int l = idx / 12288;
        int r = idx % 12288;
        int k = r / 192, j = r % 192;
        const float* wr = W + (size_t)l * 4096 + k * 64;
        const float* ir = wih + (size_t)j * 64;
        float s = 0.f;
        #pragma unroll 16
        for (int c = 0; c < 64; c++) s += __ldg(wr + c) * __ldg(ir + c);
        g_W[l][k * WROW + j] = s;
    } else {
        int idx = (b - 3365) * 256 + t;      // 0..12287
        int k = idx / 192, j = idx % 192;
        float v = __ldg(whh + (size_t)j * 64 + k);
        #pragma unroll
        for (int s = 0; s < NSTEPS; s++)
            g_W[s][k * WROW + 192 + j] = v;
    }
}

// ======================================================================
// CSR build: scan -> place. g_cnt holds degrees at scan entry.
// ======================================================================
#define SCAN_PER_T 49   // 1024 * 49 = 50176 >= NNODES
__global__ void __launch_bounds__(1024) k_scan() {
    __shared__ int wsum[32];
    int tid = threadIdx.x;
    int lane = tid & 31, wid = tid >> 5;
    int base = tid * SCAN_PER_T;

    int loc[SCAN_PER_T];
    int s = 0;
    #pragma unroll
    for (int i = 0; i < SCAN_PER_T; i++) {
        int idx = base + i;
        int c = (idx < NNODES) ? g_cnt[idx] : 0;
        loc[i] = s;
        s += c;
    }
    int v = s;
    #pragma unroll
    for (int o = 1; o < 32; o <<= 1) {
        int t = __shfl_up_sync(0xFFFFFFFFu, v, o);
        if (lane >= o) v += t;
    }
    if (lane == 31) wsum[wid] = v;
    __syncthreads();
    if (wid == 0) {
        int w = wsum[lane];
        #pragma unroll
        for (int o = 1; o < 32; o <<= 1) {
            int t = __shfl_up_sync(0xFFFFFFFFu, w, o);
            if (lane >= o) w += t;
        }
        wsum[lane] = w;
    }
    __syncthreads();
    int off = (wid > 0 ? wsum[wid - 1] : 0) + (v - s);
    #pragma unroll
    for (int i = 0; i < SCAN_PER_T; i++) {
        int idx = base + i;
        if (idx < NNODES) {
            g_row[idx] = off + loc[i];
            g_cnt[idx] = 0;              // reset as placement cursor
        }
    }
    if (tid == 0) g_row[NNODES] = NEDGES;
}

__global__ void __launch_bounds__(256) k_place(
    const int* __restrict__ src, const int* __restrict__ dst)
{
    int e = blockIdx.x * 256 + threadIdx.x;
    if (e >= NEDGES) return;
    int d = __ldg(dst + e);
    int pos = g_row[d] + atomicAdd(&g_cnt[d], 1);
    g_csr_src[pos] = __ldg(src + e);
}

// ======================================================================
// K2: FUSED gather + GRU, race-free via h double-buffering.
// 512 threads / 64 nodes per block.
// Phase 1 (per warp, 4 nodes): CSR gather-reduce of neighbor h rows from
//   the READ buffer (x at step 0) into smem m slots. 8 loads in flight.
// Phase 2: node-register-blocked (R=4) GEMM, software-pipelined weight
//   LDS (R11 core, proven), fused gates; writes the WRITE buffer.
// Last step re-zeroes g_cnt to restore the entry invariant.
// ======================================================================
#define GRU_NODES 64
#define SMEM_GRU ((64 * WROW + 64 * NROW + 2 * 192) * 4)   // 133,632 B

__global__ void __launch_bounds__(512) k_gru(
    const float* __restrict__ x,
    const float* __restrict__ bih, const float* __restrict__ bhh,
    float* __restrict__ dout, int layer, int first, int last)
{
    extern __shared__ __align__(16) float sm[];
    float* wT  = sm;                    // [64][WROW]  (+1 phantom row read-only)
    float* nd  = wT + 64 * WROW;        // [64][NROW]
    float* sbi = nd + 64 * NROW;        // [192]
    float* sbh = sbi + 192;             // [192]

    int tid = threadIdx.x;
    // Double-buffer schedule: read buf layer&1 (x at step 0), write buf (layer+1)&1.
    const float* hin = first ? x : g_h[layer & 1];
    float* hout = last ? dout : g_h[(layer + 1) & 1];

    // Restore g_cnt==0 invariant on the last step.
    if (last) {
        int ci = blockIdx.x * 512 + tid;
        if (ci < NNODES) g_cnt[ci] = 0;
    }

    // Stage combined weights (straight float4 copy)
    const float4* wsrc = (const float4*)g_W[layer];
    #pragma unroll
    for (int i = tid; i < 64 * WROW / 4; i += 512)
        ((float4*)wT)[i] = __ldg(wsrc + i);
    if (tid < 192) { sbi[tid] = __ldg(bih + tid); sbh[tid] = __ldg(bhh + tid); }

    // Stage h rows at [68..131]
    int nbase = blockIdx.x * GRU_NODES;
    for (int i = tid; i < GRU_NODES * DIM; i += 512) {
        int nl = i >> 6, k = i & 63;
        int n = nbase + nl;
        float hv = (n < NNODES) ? __ldg(hin + (size_t)n * DIM + k) : 0.f;
        nd[nl * NROW + HOFF + k] = hv;
    }

    int w = tid >> 5, lane = tid & 31;
    int half = lane >> 4, p = lane & 15;

    // Phase 1: gather m = sum of neighbor h rows, 4 nodes per warp.
    for (int q = 0; q < 4; q++) {
        int nl = w * 4 + q;
        int n = nbase + nl;
        if (n >= NNODES) break;
        int beg = __ldg(&g_row[n]);
        int end = __ldg(&g_row[n + 1]);
        float4 a0 = make_float4(0.f, 0.f, 0.f, 0.f);
        float4 a1 = make_float4(0.f, 0.f, 0.f, 0.f);
        float4 a2 = make_float4(0.f, 0.f, 0.f, 0.f);
        float4 a3 = make_float4(0.f, 0.f, 0.f, 0.f);
        int i = beg + half;
        for (; i + 6 < end; i += 8) {
            int s0 = __ldg(&g_csr_src[i]);
            int s1 = __ldg(&g_csr_src[i + 2]);
            int s2 = __ldg(&g_csr_src[i + 4]);
            int s3 = __ldg(&g_csr_src[i + 6]);
            float4 v0 = __ldg((const float4*)(hin + (size_t)s0 * DIM) + p);
            float4 v1 = __ldg((const float4*)(hin + (size_t)s1 * DIM) + p);
            float4 v2 = __ldg((const float4*)(hin + (size_t)s2 * DIM) + p);
            float4 v3 = __ldg((const float4*)(hin + (size_t)s3 * DIM) + p);
            a0.x += v0.x; a0.y += v0.y; a0.z += v0.z; a0.w += v0.w;
            a1.x += v1.x; a1.y += v1.y; a1.z += v1.z; a1.w += v1.w;
            a2.x += v2.x; a2.y += v2.y; a2.z += v2.z; a2.w += v2.w;
            a3.x += v3.x; a3.y += v3.y; a3.z += v3.z; a3.w += v3.w;
        }
        for (; i < end; i += 2) {
            int s = __ldg(&g_csr_src[i]);
            float4 v = __ldg((const float4*)(hin + (size_t)s * DIM) + p);
            a0.x += v.x; a0.y += v.y; a0.z += v.z; a0.w += v.w;
        }
        a0.x += a1.x + a2.x + a3.x;
        a0.y += a1.y + a2.y + a3.y;
        a0.z += a1.z + a2.z + a3.z;
        a0.w += a1.w + a2.w + a3.w;
        a0.x += __shfl_xor_sync(0xFFFFFFFFu, a0.x, 16);
        a0.y += __shfl_xor_sync(0xFFFFFFFFu, a0.y, 16);
        a0.z += __shfl_xor_sync(0xFFFFFFFFu, a0.z, 16);
        a0.w += __shfl_xor_sync(0xFFFFFFFFu, a0.w, 16);
        if (half == 0)
            *(float4*)(nd + nl * NROW + p * 4) = a0;
    }
    __syncthreads();

    // Phase 2: GEMM + gates (R11 core).
    int gl = lane & 15, isH = lane >> 4;
    int node0 = w * 4;

    ull acc[4][3][2];
    {
        const float* brow = isH ? sbh : sbi;
        float4 b0 = *(const float4*)(brow + 0 * 64 + gl * 4);
        float4 b1 = *(const float4*)(brow + 1 * 64 + gl * 4);
        float4 b2 = *(const float4*)(brow + 2 * 64 + gl * 4);
        #pragma unroll
        for (int n = 0; n < 4; n++) {
            acc[n][0][0] = pack2(b0.x, b0.y); acc[n][0][1] = pack2(b0.z, b0.w);
            acc[n][1][0] = pack2(b1.x, b1.y); acc[n][1][1] = pack2(b1.z, b1.w);
            acc[n][2][0] = pack2(b2.x, b2.y); acc[n][2][1] = pack2(b2.z, b2.w);
        }
    }

    const float* wb = wT + isH * 192 + gl * 4;
    const float* nb = nd + (size_t)node0 * NROW + isH * HOFF;

    ulonglong2 cw0 = *(const ulonglong2*)(wb);
    ulonglong2 cw1 = *(const ulonglong2*)(wb + 64);
    ulonglong2 cw2 = *(const ulonglong2*)(wb + 128);

    #pragma unroll 2
    for (int k4 = 0; k4 < 64; k4 += 4) {
        float4 hv0 = *(const float4*)(nb + 0 * NROW + k4);
        float4 hv1 = *(const float4*)(nb + 1 * NROW + k4);
        float4 hv2 = *(const float4*)(nb + 2 * NROW + k4);
        float4 hv3 = *(const float4*)(nb + 3 * NROW + k4);
        #pragma unroll
        for (int kk = 0; kk < 4; kk++) {
            const float* wrn = wb + (k4 + kk + 1) * WROW;
            ulonglong2 nw0 = *(const ulonglong2*)(wrn);
            ulonglong2 nw1 = *(const ulonglong2*)(wrn + 64);
            ulonglong2 nw2 = *(const ulonglong2*)(wrn + 128);

            float f0 = kk == 0 ? hv0.x : kk == 1 ? hv0.y : kk == 2 ? hv0.z : hv0.w;
            float f1 = kk == 0 ? hv1.x : kk == 1 ? hv1.y : kk == 2 ? hv1.z : hv1.w;
            float f2 = kk == 0 ? hv2.x : kk == 1 ? hv2.y : kk == 2 ? hv2.z : hv2.w;
            float f3 = kk == 0 ? hv3.x : kk == 1 ? hv3.y : kk == 2 ? hv3.z : hv3.w;
            ull x0 = pack2(f0, f0), x1 = pack2(f1, f1);
            ull x2 = pack2(f2, f2), x3 = pack2(f3, f3);
            fma2(acc[0][0][0], x0, cw0.x); fma2(acc[0][0][1], x0, cw0.y);
            fma2(acc[0][1][0], x0, cw1.x); fma2(acc[0][1][1], x0, cw1.y);
            fma2(acc[0][2][0], x0, cw2.x); fma2(acc[0][2][1], x0, cw2.y);
            fma2(acc[1][0][0], x1, cw0.x); fma2(acc[1][0][1], x1, cw0.y);
            fma2(acc[1][1][0], x1, cw1.x); fma2(acc[1][1][1], x1, cw1.y);
            fma2(acc[1][2][0], x1, cw2.x); fma2(acc[1][2][1], x1, cw2.y);
            fma2(acc[2][0][0], x2, cw0.x); fma2(acc[2][0][1], x2, cw0.y);
            fma2(acc[2][1][0], x2, cw1.x); fma2(acc[2][1][1], x2, cw1.y);
            fma2(acc[2][2][0], x2, cw2.x); fma2(acc[2][2][1], x2, cw2.y);
            fma2(acc[3][0][0], x3, cw0.x); fma2(acc[3][0][1], x3, cw0.y);
            fma2(acc[3][1][0], x3, cw1.x); fma2(acc[3][1][1], x3, cw1.y);
            fma2(acc[3][2][0], x3, cw2.x); fma2(acc[3][2][1], x3, cw2.y);

            cw0 = nw0; cw1 = nw1; cw2 = nw2;
        }
    }

    // Epilogue: per node, bring gh (lanes 16..31) to gi lanes and finish.
    #pragma unroll
    for (int n = 0; n < 4; n++) {
        ull hr0 = shfl_down16(acc[n][0][0]);
        ull hr1 = shfl_down16(acc[n][0][1]);
        ull hz0 = shfl_down16(acc[n][1][0]);
        ull hz1 = shfl_down16(acc[n][1][1]);
        ull hn0 = shfl_down16(acc[n][2][0]);
        ull hn1 = shfl_down16(acc[n][2][1]);
        int gn = nbase + node0 + n;
        if (isH == 0 && gn < NNODES) {
            float4 hold = *(const float4*)(nd + (node0 + n) * NROW + HOFF + gl * 4);
            float ho[4] = {hold.x, hold.y, hold.z, hold.w};
            float o[4];
            #pragma unroll
            for (int p2 = 0; p2 < 2; p2++) {
                float2 ir = unpack2(acc[n][0][p2]);
                float2 iz = unpack2(acc[n][1][p2]);
                float2 in = unpack2(acc[n][2][p2]);
                float2 hr = unpack2(p2 == 0 ? hr0 : hr1);
                float2 hz = unpack2(p2 == 0 ? hz0 : hz1);
                float2 hn = unpack2(p2 == 0 ? hn0 : hn1);
                float r0 = sigf(ir.x + hr.x), r1 = sigf(ir.y + hr.y);
                float z0 = sigf(iz.x + hz.x), z1 = sigf(iz.y + hz.y);
                float n0 = tanh_f(in.x + r0 * hn.x);
                float n1 = tanh_f(in.y + r1 * hn.y);
                o[2 * p2]     = (1.0f - z0) * n0 + z0 * ho[2 * p2];
                o[2 * p2 + 1] = (1.0f - z1) * n1 + z1 * ho[2 * p2 + 1];
            }
            *(float4*)(hout + (size_t)gn * DIM + gl * 4) =
                make_float4(o[0], o[1], o[2], o[3]);
        }
    }
}

// ======================================================================
extern "C" void kernel_launch(void* const* d_in, const int* in_sizes, int n_in,
                              void* d_out, int out_size)
{
    const float* x   = (const float*)d_in[0];
    const int*   ei  = (const int*)d_in[1];     // int32 (JAX x64 disabled)
    const float* W   = (const float*)d_in[2];
    const float* wih = (const float*)d_in[3];
    const float* whh = (const float*)d_in[4];
    const float* bih = (const float*)d_in[5];
    const float* bhh = (const float*)d_in[6];
    float*       out = (float*)d_out;

    const int* src = ei;
    const int* dst = ei + NEDGES;

    static int smem_set = 0;
    if (!smem_set) {
        cudaFuncSetAttribute(k_gru, cudaFuncAttributeMaxDynamicSharedMemorySize, SMEM_GRU);
        smem_set = 1;
    }

    const int g_gr = (NNODES + GRU_NODES - 1) / GRU_NODES;      // 782

    // Harness issues 2 launches first; ncu -s 5 profiles my index 3 =
    // the FIRST fused k_gru.
    k_histprep<<<3413, 256>>>(dst, W, wih, whh);                 // #0
    k_scan<<<1, 1024>>>();                                       // #1
    k_place<<<(NEDGES + 255) / 256, 256>>>(src, dst);            // #2

    for (int l = 0; l < NSTEPS; l++) {
        int first = (l == 0);
        int last  = (l == NSTEPS - 1);
        k_gru<<<g_gr, 512, SMEM_GRU>>>(x, bih, bhh, out, l, first, last); // #3..7
    }
}

// round 16
// speedup vs baseline: 1.1303x; 1.1303x over previous
#include <cuda_runtime.h>

#define NNODES 50000
#define NEDGES 800000
#define DIM 64
#define NSTEPS 5
#define WROW 384        // combined weight row: [0..191]=Wi cols, [192..383]=Wh cols
#define NROW 132        // node row: [0..63]=m(h_sum), [68..131]=h
#define HOFF 68

typedef unsigned long long ull;

// Scratch (allocation-free __device__ globals), 16B-aligned.
// g_cnt invariant: ==0 at every kernel_launch entry (zero-init at load;
// re-zeroed by the final k_gru). Every call does identical work.
__device__ __align__(16) float g_agg[NNODES * DIM];      // aggregated h-sums
__device__ __align__(16) float g_h[NNODES * DIM];        // hidden state ping buffer
__device__ __align__(16) float g_W[NSTEPS][64 * WROW];   // [k][ Wc[l] | whh^T ] combined
__device__ int g_csr_src[NEDGES];
__device__ int g_row[NNODES + 1];
__device__ int g_cnt[NNODES];

// ---------- packed f32x2 helpers ----------
__device__ __forceinline__ ull pack2(float lo, float hi) {
    ull r; asm("mov.b64 %0, {%1, %2};" : "=l"(r) : "f"(lo), "f"(hi)); return r;
}
__device__ __forceinline__ void fma2(ull& d, ull a, ull b) {
    asm("fma.rn.f32x2 %0, %1, %2, %0;" : "+l"(d) : "l"(a), "l"(b));
}
__device__ __forceinline__ float2 unpack2(ull v) {
    float2 r; asm("mov.b64 {%0, %1}, %2;" : "=f"(r.x), "=f"(r.y) : "l"(v)); return r;
}
__device__ __forceinline__ ull shfl_down16(ull v) {
    unsigned lo, hi;
    asm("mov.b64 {%0, %1}, %2;" : "=r"(lo), "=r"(hi) : "l"(v));
    lo = __shfl_down_sync(0xFFFFFFFFu, lo, 16);
    hi = __shfl_down_sync(0xFFFFFFFFu, hi, 16);
    ull r; asm("mov.b64 %0, {%1, %2};" : "=l"(r) : "r"(lo), "r"(hi));
    return r;
}
__device__ __forceinline__ float sigf(float x) { return 1.0f / (1.0f + __expf(-x)); }
__device__ __forceinline__ float tanh_f(float x) {
    float t = __expf(-2.0f * fabsf(x));
    return copysignf((1.0f - t) / (1.0f + t), x);
}

// ======================================================================
// K0: precompute combined weights (Wc[l]=W[l]@w_ih^T | whh^T) + zero agg.
// ======================================================================
__global__ void __launch_bounds__(256) k_prep(
    const float* __restrict__ W, const float* __restrict__ wih,
    const float* __restrict__ whh)
{
    int b = blockIdx.x, t = threadIdx.x;
    if (b < 240) {
        int idx = b * 256 + t;               // 0..61439
        int l = idx / 12288;
        int r = idx % 12288;
        int k = r / 192, j = r % 192;
        const float* wr = W + (size_t)l * 4096 + k * 64;
        const float* ir = wih + (size_t)j * 64;
        float s = 0.f;
        #pragma unroll 16
        for (int c = 0; c < 64; c++) s += __ldg(wr + c) * __ldg(ir + c);
        g_W[l][k * WROW + j] = s;
    } else if (b < 480) {
        int idx = (b - 240) * 256 + t;       // 0..61439
        int l = idx / 12288;
        int r = idx % 12288;
        int k = r / 192, j = r % 192;
        g_W[l][k * WROW + 192 + j] = __ldg(whh + (size_t)j * 64 + k);
    } else {
        int i = (b - 480) * 256 + t;
        if (i < NNODES * DIM / 4)
            ((float4*)g_agg)[i] = make_float4(0.f, 0.f, 0.f, 0.f);
    }
}

// ======================================================================
// Step-0 aggregate via atomic scatter (no CSR needed for step 0 -> the
// CSR build can run concurrently on a second stream).
// ======================================================================
__global__ void __launch_bounds__(256) k_scatter0(
    const float* __restrict__ x,
    const int* __restrict__ src, const int* __restrict__ dst)
{
    int t = blockIdx.x * 256 + threadIdx.x;
    int e = t >> 4;
    int p = t & 15;
    if (e >= NEDGES) return;
    int s = __ldg(src + e);
    int d = __ldg(dst + e);
    float4 v = __ldg((const float4*)(x + (size_t)s * DIM) + p);
    float* a = g_agg + (size_t)d * DIM + (size_t)p * 4;
    asm volatile("red.global.add.v4.f32 [%0], {%1, %2, %3, %4};"
                 :: "l"(a), "f"(v.x), "f"(v.y), "f"(v.z), "f"(v.w)
                 : "memory");
}

// ======================================================================
// CSR build (side stream, overlapped with prep/scatter0/gru step 0):
// histogram -> scan -> place.
// ======================================================================
__global__ void __launch_bounds__(256) k_hist(const int* __restrict__ dst) {
    int e = blockIdx.x * 256 + threadIdx.x;
    if (e < NEDGES) atomicAdd(&g_cnt[__ldg(dst + e)], 1);
}

#define SCAN_PER_T 49   // 1024 * 49 = 50176 >= NNODES
__global__ void __launch_bounds__(1024) k_scan() {
    __shared__ int wsum[32];
    int tid = threadIdx.x;
    int lane = tid & 31, wid = tid >> 5;
    int base = tid * SCAN_PER_T;

    int loc[SCAN_PER_T];
    int s = 0;
    #pragma unroll
    for (int i = 0; i < SCAN_PER_T; i++) {
        int idx = base + i;
        int c = (idx < NNODES) ? g_cnt[idx] : 0;
        loc[i] = s;
        s += c;
    }
    int v = s;
    #pragma unroll
    for (int o = 1; o < 32; o <<= 1) {
        int t = __shfl_up_sync(0xFFFFFFFFu, v, o);
        if (lane >= o) v += t;
    }
    if (lane == 31) wsum[wid] = v;
    __syncthreads();
    if (wid == 0) {
        int w = wsum[lane];
        #pragma unroll
        for (int o = 1; o < 32; o <<= 1) {
            int t = __shfl_up_sync(0xFFFFFFFFu, w, o);
            if (lane >= o) w += t;
        }
        wsum[lane] = w;
    }
    __syncthreads();
    int off = (wid > 0 ? wsum[wid - 1] : 0) + (v - s);
    #pragma unroll
    for (int i = 0; i < SCAN_PER_T; i++) {
        int idx = base + i;
        if (idx < NNODES) {
            g_row[idx] = off + loc[i];
            g_cnt[idx] = 0;              // reset as placement cursor
        }
    }
    if (tid == 0) g_row[NNODES] = NEDGES;
}

__global__ void __launch_bounds__(256) k_place(
    const int* __restrict__ src, const int* __restrict__ dst)
{
    int e = blockIdx.x * 256 + threadIdx.x;
    if (e >= NEDGES) return;
    int d = __ldg(dst + e);
    int pos = g_row[d] + atomicAdd(&g_cnt[d], 1);
    g_csr_src[pos] = __ldg(src + e);
}

// ======================================================================
// K1: gather-reduce (steps 1..4). Warp per node, 8 row-loads in flight.
// ======================================================================
__global__ void __launch_bounds__(256) k_gather() {
    int warp = (blockIdx.x * 256 + threadIdx.x) >> 5;
    if (warp >= NNODES) return;
    int lane = threadIdx.x & 31;
    int half = lane >> 4, p = lane & 15;

    int beg = __ldg(&g_row[warp]);
    int end = __ldg(&g_row[warp + 1]);

    float4 a0 = make_float4(0.f, 0.f, 0.f, 0.f);
    float4 a1 = make_float4(0.f, 0.f, 0.f, 0.f);
    float4 a2 = make_float4(0.f, 0.f, 0.f, 0.f);
    float4 a3 = make_float4(0.f, 0.f, 0.f, 0.f);
    int i = beg + half;
    for (; i + 6 < end; i += 8) {
        int s0 = __ldg(&g_csr_src[i]);
        int s1 = __ldg(&g_csr_src[i + 2]);
        int s2 = __ldg(&g_csr_src[i + 4]);
        int s3 = __ldg(&g_csr_src[i + 6]);
        float4 v0 = __ldg((const float4*)(g_h + (size_t)s0 * DIM) + p);
        float4 v1 = __ldg((const float4*)(g_h + (size_t)s1 * DIM) + p);
        float4 v2 = __ldg((const float4*)(g_h + (size_t)s2 * DIM) + p);
        float4 v3 = __ldg((const float4*)(g_h + (size_t)s3 * DIM) + p);
        a0.x += v0.x; a0.y += v0.y; a0.z += v0.z; a0.w += v0.w;
        a1.x += v1.x; a1.y += v1.y; a1.z += v1.z; a1.w += v1.w;
        a2.x += v2.x; a2.y += v2.y; a2.z += v2.z; a2.w += v2.w;
        a3.x += v3.x; a3.y += v3.y; a3.z += v3.z; a3.w += v3.w;
    }
    for (; i < end; i += 2) {
        int s = __ldg(&g_csr_src[i]);
        float4 v = __ldg((const float4*)(g_h + (size_t)s * DIM) + p);
        a0.x += v.x; a0.y += v.y; a0.z += v.z; a0.w += v.w;
    }
    a0.x += a1.x + a2.x + a3.x;
    a0.y += a1.y + a2.y + a3.y;
    a0.z += a1.z + a2.z + a3.z;
    a0.w += a1.w + a2.w + a3.w;
    a0.x += __shfl_xor_sync(0xFFFFFFFFu, a0.x, 16);
    a0.y += __shfl_xor_sync(0xFFFFFFFFu, a0.y, 16);
    a0.z += __shfl_xor_sync(0xFFFFFFFFu, a0.z, 16);
    a0.w += __shfl_xor_sync(0xFFFFFFFFu, a0.w, 16);
    if (half == 0)
        ((float4*)(g_agg + (size_t)warp * DIM))[p] = a0;
}

// ======================================================================
// K2: GRU, node-register-blocked (R=4), software-pipelined weight LDS
// (R11 core, proven at 107 us/step). Last step re-zeroes g_cnt.
// ======================================================================
#define GRU_NODES 64
#define SMEM_GRU ((64 * WROW + 64 * NROW + 2 * 192) * 4)   // 133,632 B

__global__ void __launch_bounds__(512) k_gru(
    const float* __restrict__ x,
    const float* __restrict__ bih, const float* __restrict__ bhh,
    float* __restrict__ dout, int layer, int first, int last)
{
    extern __shared__ __align__(16) float sm[];
    float* wT  = sm;                    // [64][WROW]  (+1 phantom row read-only)
    float* nd  = wT + 64 * WROW;        // [64][NROW]
    float* sbi = nd + 64 * NROW;        // [192]
    float* sbh = sbi + 192;             // [192]

    int tid = threadIdx.x;
    const float* hin = first ? x : g_h;
    float* hout = last ? dout : g_h;

    // Restore g_cnt==0 invariant on the last step.
    if (last) {
        int ci = blockIdx.x * 512 + tid;
        if (ci < NNODES) g_cnt[ci] = 0;
    }

    // Stage combined weights (straight float4 copy)
    const float4* wsrc = (const float4*)g_W[layer];
    #pragma unroll
    for (int i = tid; i < 64 * WROW / 4; i += 512)
        ((float4*)wT)[i] = __ldg(wsrc + i);
    if (tid < 192) { sbi[tid] = __ldg(bih + tid); sbh[tid] = __ldg(bhh + tid); }

    // Stage node rows: m at [0..63], h at [68..131]
    int nbase = blockIdx.x * GRU_NODES;
    for (int i = tid; i < GRU_NODES * DIM; i += 512) {
        int nl = i >> 6, k = i & 63;
        int n = nbase + nl;
        float mv = 0.f, hv = 0.f;
        if (n < NNODES) {
            mv = __ldg(g_agg + (size_t)n * DIM + k);
            hv = __ldg(hin + (size_t)n * DIM + k);
        }
        nd[nl * NROW + k] = mv;
        nd[nl * NROW + HOFF + k] = hv;
    }
    __syncthreads();

    int w = tid >> 5, lane = tid & 31;
    int gl = lane & 15, isH = lane >> 4;
    int node0 = w * 4;

    // acc[node][gate][pair]: 24 ull
    ull acc[4][3][2];
    {
        const float* brow = isH ? sbh : sbi;
        float4 b0 = *(const float4*)(brow + 0 * 64 + gl * 4);
        float4 b1 = *(const float4*)(brow + 1 * 64 + gl * 4);
        float4 b2 = *(const float4*)(brow + 2 * 64 + gl * 4);
        #pragma unroll
        for (int n = 0; n < 4; n++) {
            acc[n][0][0] = pack2(b0.x, b0.y); acc[n][0][1] = pack2(b0.z, b0.w);
            acc[n][1][0] = pack2(b1.x, b1.y); acc[n][1][1] = pack2(b1.z, b1.w);
            acc[n][2][0] = pack2(b2.x, b2.y); acc[n][2][1] = pack2(b2.z, b2.w);
        }
    }

    const float* wb = wT + isH * 192 + gl * 4;
    const float* nb = nd + (size_t)node0 * NROW + isH * HOFF;

    // Prime the weight pipeline with k=0
    ulonglong2 cw0 = *(const ulonglong2*)(wb);
    ulonglong2 cw1 = *(const ulonglong2*)(wb + 64);
    ulonglong2 cw2 = *(const ulonglong2*)(wb + 128);

    #pragma unroll 2
    for (int k4 = 0; k4 < 64; k4 += 4) {
        float4 hv0 = *(const float4*)(nb + 0 * NROW + k4);
        float4 hv1 = *(const float4*)(nb + 1 * NROW + k4);
        float4 hv2 = *(const float4*)(nb + 2 * NROW + k4);
        float4 hv3 = *(const float4*)(nb + 3 * NROW + k4);
        #pragma unroll
        for (int kk = 0; kk < 4; kk++) {
            // Prefetch weights for k+1 (row 64 at the very end: harmless)
            const float* wrn = wb + (k4 + kk + 1) * WROW;
            ulonglong2 nw0 = *(const ulonglong2*)(wrn);
            ulonglong2 nw1 = *(const ulonglong2*)(wrn + 64);
            ulonglong2 nw2 = *(const ulonglong2*)(wrn + 128);

            float f0 = kk == 0 ? hv0.x : kk == 1 ? hv0.y : kk == 2 ? hv0.z : hv0.w;
            float f1 = kk == 0 ? hv1.x : kk == 1 ? hv1.y : kk == 2 ? hv1.z : hv1.w;
            float f2 = kk == 0 ? hv2.x : kk == 1 ? hv2.y : kk == 2 ? hv2.z : hv2.w;
            float f3 = kk == 0 ? hv3.x : kk == 1 ? hv3.y : kk == 2 ? hv3.z : hv3.w;
            ull x0 = pack2(f0, f0), x1 = pack2(f1, f1);
            ull x2 = pack2(f2, f2), x3 = pack2(f3, f3);
            fma2(acc[0][0][0], x0, cw0.x); fma2(acc[0][0][1], x0, cw0.y);
            fma2(acc[0][1][0], x0, cw1.x); fma2(acc[0][1][1], x0, cw1.y);
            fma2(acc[0][2][0], x0, cw2.x); fma2(acc[0][2][1], x0, cw2.y);
            fma2(acc[1][0][0], x1, cw0.x); fma2(acc[1][0][1], x1, cw0.y);
            fma2(acc[1][1][0], x1, cw1.x); fma2(acc[1][1][1], x1, cw1.y);
            fma2(acc[1][2][0], x1, cw2.x); fma2(acc[1][2][1], x1, cw2.y);
            fma2(acc[2][0][0], x2, cw0.x); fma2(acc[2][0][1], x2, cw0.y);
            fma2(acc[2][1][0], x2, cw1.x); fma2(acc[2][1][1], x2, cw1.y);
            fma2(acc[2][2][0], x2, cw2.x); fma2(acc[2][2][1], x2, cw2.y);
            fma2(acc[3][0][0], x3, cw0.x); fma2(acc[3][0][1], x3, cw0.y);
            fma2(acc[3][1][0], x3, cw1.x); fma2(acc[3][1][1], x3, cw1.y);
            fma2(acc[3][2][0], x3, cw2.x); fma2(acc[3][2][1], x3, cw2.y);

            cw0 = nw0; cw1 = nw1; cw2 = nw2;
        }
    }

    // Epilogue: per node, bring gh (lanes 16..31) to gi lanes and finish.
    #pragma unroll
    for (int n = 0; n < 4; n++) {
        ull hr0 = shfl_down16(acc[n][0][0]);
        ull hr1 = shfl_down16(acc[n][0][1]);
        ull hz0 = shfl_down16(acc[n][1][0]);
        ull hz1 = shfl_down16(acc[n][1][1]);
        ull hn0 = shfl_down16(acc[n][2][0]);
        ull hn1 = shfl_down16(acc[n][2][1]);
        int gn = nbase + node0 + n;
        if (isH == 0 && gn < NNODES) {
            float4 hold = *(const float4*)(nd + (node0 + n) * NROW + HOFF + gl * 4);
            float ho[4] = {hold.x, hold.y, hold.z, hold.w};
            float o[4];
            #pragma unroll
            for (int p2 = 0; p2 < 2; p2++) {
                float2 ir = unpack2(acc[n][0][p2]);
                float2 iz = unpack2(acc[n][1][p2]);
                float2 in = unpack2(acc[n][2][p2]);
                float2 hr = unpack2(p2 == 0 ? hr0 : hr1);
                float2 hz = unpack2(p2 == 0 ? hz0 : hz1);
                float2 hn = unpack2(p2 == 0 ? hn0 : hn1);
                float r0 = sigf(ir.x + hr.x), r1 = sigf(ir.y + hr.y);
                float z0 = sigf(iz.x + hz.x), z1 = sigf(iz.y + hz.y);
                float n0 = tanh_f(in.x + r0 * hn.x);
                float n1 = tanh_f(in.y + r1 * hn.y);
                o[2 * p2]     = (1.0f - z0) * n0 + z0 * ho[2 * p2];
                o[2 * p2 + 1] = (1.0f - z1) * n1 + z1 * ho[2 * p2 + 1];
            }
            *(float4*)(hout + (size_t)gn * DIM + gl * 4) =
                make_float4(o[0], o[1], o[2], o[3]);
        }
    }
}

// ======================================================================
extern "C" void kernel_launch(void* const* d_in, const int* in_sizes, int n_in,
                              void* d_out, int out_size)
{
    const float* x   = (const float*)d_in[0];
    const int*   ei  = (const int*)d_in[1];     // int32 (JAX x64 disabled)
    const float* W   = (const float*)d_in[2];
    const float* wih = (const float*)d_in[3];
    const float* whh = (const float*)d_in[4];
    const float* bih = (const float*)d_in[5];
    const float* bhh = (const float*)d_in[6];
    float*       out = (float*)d_out;

    const int* src = ei;
    const int* dst = ei + NEDGES;

    // One-time resource setup (same static-guard pattern as prior rounds;
    // no device-memory allocation in the launch path).
    static int init_done = 0;
    static cudaStream_t s2;
    static cudaEvent_t ev_fork, ev_join;
    if (!init_done) {
        cudaFuncSetAttribute(k_gru, cudaFuncAttributeMaxDynamicSharedMemorySize, SMEM_GRU);
        cudaStreamCreateWithFlags(&s2, cudaStreamNonBlocking);
        cudaEventCreateWithFlags(&ev_fork, cudaEventDisableTiming);
        cudaEventCreateWithFlags(&ev_join, cudaEventDisableTiming);
        init_done = 1;
    }

    const int g_ga = (NNODES * 32 + 255) / 256;                 // 6250
    const int g_gr = (NNODES + GRU_NODES - 1) / GRU_NODES;      // 782
    const int g_sc = (NEDGES * 16) / 256;                       // 50000

    // Fork: CSR build (hist/scan/place) depends only on dst and the
    // g_cnt==0 invariant -> run it on s2 concurrently with the main
    // stream's prep + scatter0 + gru step 0 (which don't need the CSR).
    cudaEventRecord(ev_fork, 0);
    cudaStreamWaitEvent(s2, ev_fork, 0);
    k_hist<<<(NEDGES + 255) / 256, 256, 0, s2>>>(dst);
    k_scan<<<1, 1024, 0, s2>>>();
    k_place<<<(NEDGES + 255) / 256, 256, 0, s2>>>(src, dst);
    cudaEventRecord(ev_join, s2);

    // Main stream: weights + agg zero, step-0 scatter, step-0 GRU.
    k_prep<<<3605, 256>>>(W, wih, whh);
    k_scatter0<<<g_sc, 256>>>(x, src, dst);
    k_gru<<<g_gr, 512, SMEM_GRU>>>(x, bih, bhh, out, 0, 1, 0);

    // Join: gathers from step 1 on need the finished CSR.
    cudaStreamWaitEvent(0, ev_join, 0);

    for (int l = 1; l < NSTEPS; l++) {
        int last = (l == NSTEPS - 1);
        k_gather<<<g_ga, 256>>>();
        k_gru<<<g_gr, 512, SMEM_GRU>>>(x, bih, bhh, out, l, 0, last);
    }
}